// round 11
// baseline (speedup 1.0000x reference)
#include <cuda_runtime.h>
#include <cstdint>
#include <cstddef>

#define NFEAT 17
#define HDIM 8
#define BSZ 256
#define TSTEPS 512
#define XDIM 59
#define CHK 32
#define NCHK (TSTEPS/CHK)
#define BPC 2
#define NTHREADS 160
#define ROWPAD (CHK*XDIM + 16)   // chunk + zeroed pad for pair overread

typedef unsigned long long u64;

// slot = tid>>3 (20 slots, 5 warps). 2-chain threads handle their feature for
// BOTH batches (weights shared). w3 = heavy features, alone on SMSP3.
// w4 = f16 single-chain (slots 16,17 = batch 0,1), co-resident on SMSP0.
__device__ __constant__ int8_t c_slot_f[20] = {
   0, 5, 6, 7,   8, 9,10,11,  12,13,14,15,   3, 2, 4, 1,  16,16,16,16};
__device__ __constant__ int8_t c_slot_b1[20] = {
   0, 0, 0, 0,   0, 0, 0, 0,   0, 0, 0, 0,   0, 0, 0, 0,   0, 1, 0, 1};
__device__ __constant__ int8_t c_slot_wr[20] = {
   1, 1, 1, 1,   1, 1, 1, 1,   1, 1, 1, 1,   1, 1, 1, 1,   1, 1, 0, 0};
// segment start offsets (cumsum of DIMS)
__device__ __constant__ int8_t c_start[17] =
  {0,2,10,22,35,47,48,49,50,51,52,53,54,55,56,57,58};

template<int N> struct IC { static constexpr int value = N; };

__device__ __forceinline__ void cp16(uint32_t s, const float* g){
  asm volatile("cp.async.ca.shared.global [%0], [%1], 16;" :: "r"(s), "l"(g) : "memory");
}
__device__ __forceinline__ float tanh_ap(float x){
  float y; asm("tanh.approx.f32 %0, %1;" : "=f"(y) : "f"(x)); return y;
}
__device__ __forceinline__ u64 pk(float lo, float hi){
  u64 r; asm("mov.b64 %0,{%1,%2};" : "=l"(r) : "f"(lo), "f"(hi)); return r;
}
__device__ __forceinline__ void upk(float& lo, float& hi, u64 p){
  asm("mov.b64 {%0,%1},%2;" : "=f"(lo), "=f"(hi) : "l"(p));
}
__device__ __forceinline__ u64 fma2(u64 a, u64 b, u64 c){
  u64 d; asm("fma.rn.f32x2 %0,%1,%2,%3;" : "=l"(d) : "l"(a), "l"(b), "l"(c)); return d;
}
__device__ __forceinline__ u64 add2(u64 a, u64 b){
  u64 d; asm("add.rn.f32x2 %0,%1,%2;" : "=l"(d) : "l"(a), "l"(b)); return d;
}
__device__ __forceinline__ float hsum(u64 p){
  float lo, hi; upk(lo, hi, p); return lo + hi;
}
__device__ __forceinline__ u64 asu(double d){ return __double_as_longlong(d); }

extern "C" __global__ void __launch_bounds__(NTHREADS, 1)
mcgru_kernel(const float* __restrict__ x,   const float* __restrict__ Wih,
             const float* __restrict__ Whh, const float* __restrict__ bih,
             const float* __restrict__ bhh, float* __restrict__ out)
{
  __shared__ __align__(16) float xs[2][BPC][ROWPAD];   // 30.5 KB, R4 layout

  const int tid  = threadIdx.x;
  const int w    = tid >> 5;
  const int slot = tid >> 3;
  const int j    = tid & 7;
  const int f    = c_slot_f[slot];
  const int bl1  = c_slot_b1[slot];       // batch for 1-chain warp
  const bool wen = (bool)c_slot_wr[slot];
  const int startf = c_start[f];
  const int p0   = startf & 1;
  const int bg0  = blockIdx.x * BPC;

  // zero the overread pads once (data region overwritten by staging)
  for (int i = tid; i < 16; i += NTHREADS){
    xs[0][0][CHK*XDIM + i] = 0.f; xs[0][1][CHK*XDIM + i] = 0.f;
    xs[1][0][CHK*XDIM + i] = 0.f; xs[1][1][CHK*XDIM + i] = 0.f;
  }

  // ---- dual-parity weight pair sets (R8-proven logic).
  // Even-tl base = startf + 59*tl - ((p0+tl)&1): wE on even tl, wO on odd.
  // r/z pre-scaled 0.5 (sigmoid(x)=.5+.5*tanh(x/2)).
  u64 wEr[7], wEz[7], wEn[7], wOr[7], wOz[7], wOn[7];
  {
    const float* Wf = Wih + f*24*13;
    auto wat = [&](int row, int d)->float {
      return (d >= 0 && d < 13) ? Wf[row*13 + d] : 0.f;   // Wih zero-masked past true d
    };
    #pragma unroll
    for (int p = 0; p < 7; ++p){
      int a0 = 2*p, a1 = 2*p+1, s0 = 2*p-1, s1 = 2*p;
      u64 rA = pk(0.5f*wat(0+j,a0),  0.5f*wat(0+j,a1));
      u64 rS = pk(0.5f*wat(0+j,s0),  0.5f*wat(0+j,s1));
      u64 zA = pk(0.5f*wat(8+j,a0),  0.5f*wat(8+j,a1));
      u64 zS = pk(0.5f*wat(8+j,s0),  0.5f*wat(8+j,s1));
      u64 nA = pk(wat(16+j,a0), wat(16+j,a1));
      u64 nS = pk(wat(16+j,s0), wat(16+j,s1));
      wEr[p] = p0 ? rS : rA;  wOr[p] = p0 ? rA : rS;
      wEz[p] = p0 ? zS : zA;  wOz[p] = p0 ? zA : zS;
      wEn[p] = p0 ? nS : nA;  wOn[p] = p0 ? nA : nS;
    }
  }
  u64 urp[4], uzp[4], unp[4];
  {
    const float* Uf = Whh + f*24*8;
    #pragma unroll
    for (int p = 0; p < 4; ++p){
      urp[p] = pk(0.5f*Uf[(0 + j)*8 + 2*p], 0.5f*Uf[(0 + j)*8 + 2*p+1]);
      uzp[p] = pk(0.5f*Uf[(8 + j)*8 + 2*p], 0.5f*Uf[(8 + j)*8 + 2*p+1]);
      unp[p] = pk(0.5f*Uf[(16 + j)*8 + 2*p], 0.5f*Uf[(16 + j)*8 + 2*p+1]);
    }
  }
  const u64 brp  = pk(0.5f*(bih[f*24 + j]     + bhh[f*24 + j]),     0.f);
  const u64 bzp  = pk(0.5f*(bih[f*24 + 8 + j] + bhh[f*24 + 8 + j]), 0.f);
  const u64 bxnp = pk(bih[f*24 + 16 + j], 0.f);
  const u64 bhnp = pk(0.5f*bhh[f*24 + 16 + j], 0.f);
  const u64 Z64  = 0ULL;

  // ---- staging: R4-proven contiguous 16B cp.async
  auto stage = [&](int c, int buf){
    #pragma unroll
    for (int blx = 0; blx < BPC; ++blx){
      const float* src = x + ((size_t)(bg0 + blx)*TSTEPS + (size_t)c*CHK)*XDIM;
      uint32_t dst = (uint32_t)__cvta_generic_to_shared(&xs[buf][blx][0]);
      for (int i = tid; i < (CHK*XDIM)/4; i += NTHREADS)
        cp16(dst + (uint32_t)i*16u, src + i*4);
    }
  };

  stage(0, 0); asm volatile("cp.async.commit_group;" ::: "memory");
  stage(1, 1); asm volatile("cp.async.commit_group;" ::: "memory");

  float h0 = 0.f, h1 = 0.f;            // chain states (chain1 unused if NCH==1)
  float* outA = out + (((size_t)(bg0 + 0)*TSTEPS)*NFEAT + f)*HDIM + j;
  float* outB = out + (((size_t)(bg0 + 1)*TSTEPS)*NFEAT + f)*HDIM + j;

  // NCH chains per thread (2 = both batches, weights shared).
  auto run_chunk = [&](auto DPc, auto NCHc, int buf, float* oA, float* oB){
    constexpr int DP  = decltype(DPc)::value;
    constexpr int NCH = decltype(NCHc)::value;
    const float* pl0 = (NCH == 2) ? &xs[buf][0][0] : &xs[buf][bl1][0];
    const float* pl1 = &xs[buf][1][0];
    // single-chain slots write to their own batch's output
    float* o0 = (NCH == 2 || bl1 == 0) ? oA : oB;
    const double* xE0 = (const double*)(pl0 + (startf - p0));
    const double* xO0 = (const double*)(pl0 + (startf + 58 + p0));
    const double* xE1 = (const double*)(pl1 + (startf - p0));
    const double* xO1 = (const double*)(pl1 + (startf + 58 + p0));

    auto gates = [&](u64 gr, u64 gz, u64 gn, float hcur)->float{
      float hk0 = __shfl_sync(0xFFFFFFFFu, hcur, 0, 8);
      float hk1 = __shfl_sync(0xFFFFFFFFu, hcur, 1, 8);
      float hk2 = __shfl_sync(0xFFFFFFFFu, hcur, 2, 8);
      float hk3 = __shfl_sync(0xFFFFFFFFu, hcur, 3, 8);
      float hk4 = __shfl_sync(0xFFFFFFFFu, hcur, 4, 8);
      float hk5 = __shfl_sync(0xFFFFFFFFu, hcur, 5, 8);
      float hk6 = __shfl_sync(0xFFFFFFFFu, hcur, 6, 8);
      float hk7 = __shfl_sync(0xFFFFFFFFu, hcur, 7, 8);
      u64 H01 = pk(hk0,hk1), H23 = pk(hk2,hk3), H45 = pk(hk4,hk5), H67 = pk(hk6,hk7);

      u64 rA = fma2(urp[0], H01, gr);  rA = fma2(urp[1], H23, rA);
      u64 rB = fma2(urp[2], H45, Z64); rB = fma2(urp[3], H67, rB);
      float tr = tanh_ap(hsum(add2(rA, rB)));

      u64 zA = fma2(uzp[0], H01, gz);  zA = fma2(uzp[1], H23, zA);
      u64 zB = fma2(uzp[2], H45, Z64); zB = fma2(uzp[3], H67, zB);
      float tz = tanh_ap(hsum(add2(zA, zB)));

      u64 nA = fma2(unp[0], H01, bhnp); nA = fma2(unp[1], H23, nA);
      u64 nB = fma2(unp[2], H45, Z64);  nB = fma2(unp[3], H67, nB);
      u64 nacc = add2(nA, nB);
      float hnh = hsum(nacc);                 // 0.5*(Un h + bhn)
      float s   = hsum(gn) + hnh;             // gn + hnh
      float a   = fmaf(tr, hnh, s);           // gn + r*(Un h + bhn)
      float n   = tanh_ap(a);
      float uu  = 0.5f*(hcur - n);
      return fmaf(tz, uu, n + uu);            // (1-z)*n + z*h
    };

    auto step = [&](const double* xpA, const double* xpB,
                    const u64 (&wr)[7], const u64 (&wz)[7], const u64 (&wn)[7],
                    float* sA, float* sB){
      // gx for both chains first (independent of h — fills stall shadows)
      u64 grA = brp, gzA = bzp, gnA = bxnp;
      u64 grB = brp, gzB = bzp, gnB = bxnp;
      #pragma unroll
      for (int p = 0; p < DP; ++p){
        u64 XA = asu(xpA[p]);
        grA = fma2(wr[p], XA, grA);
        gzA = fma2(wz[p], XA, gzA);
        gnA = fma2(wn[p], XA, gnA);
        if constexpr (NCH == 2){
          u64 XB = asu(xpB[p]);
          grB = fma2(wr[p], XB, grB);
          gzB = fma2(wz[p], XB, gzB);
          gnB = fma2(wn[p], XB, gnB);
        }
      }
      h0 = gates(grA, gzA, gnA, h0);
      if (wen) *sA = h0;
      if constexpr (NCH == 2){
        h1 = gates(grB, gzB, gnB, h1);
        if (wen) *sB = h1;
      }
    };

    #pragma unroll 2
    for (int t2 = 0; t2 < CHK/2; ++t2){
      size_t oE = (size_t)(2*t2)*(NFEAT*HDIM), oO = (size_t)(2*t2+1)*(NFEAT*HDIM);
      step(xE0 + t2*XDIM, xE1 + t2*XDIM, wEr, wEz, wEn, o0 + oE, oB + oE);
      step(xO0 + t2*XDIM, xO1 + t2*XDIM, wOr, wOz, wOn, o0 + oO, oB + oO);
    }
  };

  for (int c = 0; c < NCHK; ++c){
    asm volatile("cp.async.wait_group 1;" ::: "memory");
    __syncthreads();
    float* oA = outA + (size_t)c*CHK*(NFEAT*HDIM);
    float* oB = outB + (size_t)c*CHK*(NFEAT*HDIM);

    if (w == 3)       run_chunk(IC<7>{}, IC<2>{}, c & 1, oA, oB);   // heavy
    else if (w == 4)  run_chunk(IC<1>{}, IC<1>{}, c & 1, oA, oB);   // f16 single
    else if (w == 0)  run_chunk(IC<2>{}, IC<2>{}, c & 1, oA, oB);   // f0 needs DP=2 (odd-parity dim coverage)
    else              run_chunk(IC<1>{}, IC<2>{}, c & 1, oA, oB);   // light d=1

    __syncthreads();                          // buffer free before restage
    if (c + 2 < NCHK) stage(c + 2, c & 1);
    asm volatile("cp.async.commit_group;" ::: "memory");
  }
}

extern "C" void kernel_launch(void* const* d_in, const int* in_sizes, int n_in,
                              void* d_out, int out_size)
{
  const float* x   = (const float*)d_in[0];
  const float* Wih = (const float*)d_in[1];
  const float* Whh = (const float*)d_in[2];
  const float* bih = (const float*)d_in[3];
  const float* bhh = (const float*)d_in[4];
  (void)in_sizes; (void)n_in; (void)out_size;
  mcgru_kernel<<<BSZ/BPC, NTHREADS>>>(x, Wih, Whh, bih, bhh, (float*)d_out);
}